// round 7
// baseline (speedup 1.0000x reference)
#include <cuda_runtime.h>

// SpatialTransformer: 3D trilinear warp — direct gather, warp-along-z mapping.
// vol: [B=2, 160, 192, 160, 1] f32 ; trf: [..., 3] f32 ; out like vol.
//
// One thread = one voxel; consecutive threads = consecutive z. DZ = 160 = 5*32,
// so every warp's 32 lanes lie in ONE (b,x,y) row, spanning 32 consecutive z.
// Each of the 8 corner gathers therefore touches a single contiguous ~140B
// span (plus per-lane jitter) -> ~2 L1tex wavefronts per gather instead of
// ~6 with multi-row warps. No shared memory, no syncs, high occupancy.
// Volume (19.7 MB/batch) lives in L2, so the 8x gather amplification is
// absorbed by L2, not DRAM.

#define DX 160
#define DY 192
#define DZ 160
#define NB 2
#define NVOX (NB * DX * DY * DZ)

__global__ __launch_bounds__(256)
void warp_direct_kernel(const float* __restrict__ vol,
                        const float* __restrict__ trf,
                        float* __restrict__ out)
{
    const int t = blockIdx.x * 256 + threadIdx.x;   // grid sized exactly

    // decompose: t = ((b*DX + x)*DY + y)*DZ + z
    const int z = t % DZ;
    int r = t / DZ;
    const int y = r % DY;
    r /= DY;
    const int x = r % DX;
    const int b = r / DX;

    const float* __restrict__ v = vol + (size_t)b * (DX * DY * DZ);

    const float tx = __ldg(trf + (size_t)t * 3 + 0);
    const float ty = __ldg(trf + (size_t)t * 3 + 1);
    const float tz = __ldg(trf + (size_t)t * 3 + 2);

    float lx = fminf(fmaxf((float)x + tx, 0.0f), (float)(DX - 1));
    float ly = fminf(fmaxf((float)y + ty, 0.0f), (float)(DY - 1));
    float lz = fminf(fmaxf((float)z + tz, 0.0f), (float)(DZ - 1));

    int ix0 = (int)floorf(lx);
    int iy0 = (int)floorf(ly);
    int iz0 = (int)floorf(lz);
    int ix1 = min(ix0 + 1, DX - 1);
    int iy1 = min(iy0 + 1, DY - 1);
    int iz1 = min(iz0 + 1, DZ - 1);

    float wx1 = (float)ix1 - lx;   // lower-corner weight (d1 in reference)
    float wy1 = (float)iy1 - ly;
    float wz1 = (float)iz1 - lz;
    float wx0 = 1.0f - wx1;
    float wy0 = 1.0f - wy1;
    float wz0 = 1.0f - wz1;

    const float* p00 = v + ((size_t)ix0 * DY + iy0) * DZ;
    const float* p01 = v + ((size_t)ix0 * DY + iy1) * DZ;
    const float* p10 = v + ((size_t)ix1 * DY + iy0) * DZ;
    const float* p11 = v + ((size_t)ix1 * DY + iy1) * DZ;

    float v000 = __ldg(p00 + iz0), v001 = __ldg(p00 + iz1);
    float v010 = __ldg(p01 + iz0), v011 = __ldg(p01 + iz1);
    float v100 = __ldg(p10 + iz0), v101 = __ldg(p10 + iz1);
    float v110 = __ldg(p11 + iz0), v111 = __ldg(p11 + iz1);

    float c00 = v000 * wz1 + v001 * wz0;
    float c01 = v010 * wz1 + v011 * wz0;
    float c10 = v100 * wz1 + v101 * wz0;
    float c11 = v110 * wz1 + v111 * wz0;

    float c0 = c00 * wy1 + c01 * wy0;
    float c1 = c10 * wy1 + c11 * wy0;

    out[t] = c0 * wx1 + c1 * wx0;
}

extern "C" void kernel_launch(void* const* d_in, const int* in_sizes, int n_in,
                              void* d_out, int out_size)
{
    const float* vol = (const float*)d_in[0];
    const float* trf = (const float*)d_in[1];
    float* out = (float*)d_out;

    const int blocks = NVOX / 256;   // 38400, exact
    warp_direct_kernel<<<blocks, 256>>>(vol, trf, out);
}

// round 8
// speedup vs baseline: 1.0288x; 1.0288x over previous
#include <cuda_runtime.h>

// SpatialTransformer: 3D trilinear warp, smem-tiled, ILP-4 (R3 structure),
// tile squeezed to 44.5 KB so 5 blocks fit per SM (was 4).
// vol: [B=2, 160, 192, 160, 1] f32 ; trf: [..., 3] f32 ; out like vol.
//
// Block = 16x16x16 output tile. Smem tile 22(x) x 22(y) x 23(z) floats,
// z covers [z0-4 .. z0+18] (max needed corner is z0+18). Each thread: 4
// consecutive z voxels (float4 trf load, float4 out store), 4 x-quads.
// Out-of-tile corners (~0.5%) use the exact global fallback.

#define DX 160
#define DY 192
#define DZ 160
#define NB 2
#define TS 16
#define SX 22          // x extent: [x0-3 .. x0+18]
#define SY 22          // y extent: [y0-3 .. y0+18]
#define SZ 23          // z extent: [z0-4 .. z0+18]
#define SZP 23         // z row stride
#define SELEMS (SX*SY*SZP)   // 11132 floats = 44528 B

extern __shared__ float tile[];

__device__ __forceinline__ int iclamp(int v, int hi) {
    return min(max(v, 0), hi);
}

__global__ __launch_bounds__(256, 5)
void warp_tile8_kernel(const float* __restrict__ vol,
                       const float* __restrict__ trf,
                       float* __restrict__ out)
{
    const int tid = threadIdx.x;
    const int b  = blockIdx.z / (DX / TS);
    const int x0 = (blockIdx.z % (DX / TS)) * TS;
    const int y0 = blockIdx.y * TS;
    const int z0 = blockIdx.x * TS;

    const float* __restrict__ v = vol + (size_t)b * (DX * DY * DZ);
    const int xlo = x0 - 3, ylo = y0 - 3, zlo = z0 - 4;

    // ---------------- cooperative tile load ----------------
    if (zlo >= 0 && z0 + 18 <= DZ - 1) {
        // z-interior: 23 z values = 5 aligned float4 (z 0..19) + 3 scalars
        // ((z0-4)*4 bytes is 16B-aligned since z0 % 16 == 0)
        for (int idx = tid; idx < SX * SY * 8; idx += 256) {
            int c   = idx & 7;
            int row = idx >> 3;
            int py  = row % SY;
            int px  = row / SY;
            int gx  = iclamp(xlo + px, DX - 1);
            int gy  = iclamp(ylo + py, DY - 1);
            const float* src = v + ((size_t)gx * DY + gy) * DZ + zlo;
            float* dst = &tile[(px * SY + py) * SZP];
            if (c < 5) {
                float4 val = __ldg(reinterpret_cast<const float4*>(src) + c);
                dst[c * 4 + 0] = val.x;
                dst[c * 4 + 1] = val.y;
                dst[c * 4 + 2] = val.z;
                dst[c * 4 + 3] = val.w;
            } else {
                int zz = 15 + c;      // c=5,6,7 -> z offset 20,21,22
                dst[zz] = __ldg(src + zz);
            }
        }
    } else {
        // z-border: scalar clamped load
        for (int idx = tid; idx < SX * SY * SZ; idx += 256) {
            int pz = idx % SZ;
            int r  = idx / SZ;
            int py = r % SY;
            int px = r / SY;
            int gx = iclamp(xlo + px, DX - 1);
            int gy = iclamp(ylo + py, DY - 1);
            int gz = iclamp(zlo + pz, DZ - 1);
            tile[(px * SY + py) * SZP + pz] =
                __ldg(v + ((size_t)gx * DY + gy) * DZ + gz);
        }
    }
    __syncthreads();

    // ---------------- per-voxel warp, 4 z-voxels per thread ----------------
    const int zg = tid & 3;            // z quad within tile (0..3)
    const int vy = (tid >> 2) & 15;    // 0..15
    const int xs = tid >> 6;           // 0..3
    const int gy = y0 + vy;
    const int zb = z0 + zg * 4;

    const float4* __restrict__ trf4 = reinterpret_cast<const float4*>(trf);
    float4* __restrict__ out4 = reinterpret_cast<float4*>(out);

#pragma unroll 1
    for (int it = 0; it < 4; ++it) {
        const int gx = x0 + it * 4 + xs;
        const size_t g = (((size_t)b * DX + gx) * DY + gy) * (DZ / 4)
                         + (z0 >> 2) + zg;

        float4 t0 = __ldg(&trf4[g * 3 + 0]);
        float4 t1 = __ldg(&trf4[g * 3 + 1]);
        float4 t2 = __ldg(&trf4[g * 3 + 2]);

        float tx[4] = {t0.x, t0.w, t1.z, t2.y};
        float ty[4] = {t0.y, t1.x, t1.w, t2.z};
        float tz[4] = {t0.z, t1.y, t2.x, t2.w};

        float4 res;
        float* rp = reinterpret_cast<float*>(&res);

#pragma unroll
        for (int j = 0; j < 4; ++j) {
            float lx = fminf(fmaxf((float)gx + tx[j],       0.0f), (float)(DX - 1));
            float ly = fminf(fmaxf((float)gy + ty[j],       0.0f), (float)(DY - 1));
            float lz = fminf(fmaxf((float)(zb + j) + tz[j], 0.0f), (float)(DZ - 1));

            int ix0 = (int)floorf(lx);
            int iy0 = (int)floorf(ly);
            int iz0 = (int)floorf(lz);
            int ix1 = min(ix0 + 1, DX - 1);
            int iy1 = min(iy0 + 1, DY - 1);
            int iz1 = min(iz0 + 1, DZ - 1);

            float wx1 = (float)ix1 - lx;    // lower-corner weight (d1)
            float wy1 = (float)iy1 - ly;
            float wz1 = (float)iz1 - lz;
            float wx0 = 1.0f - wx1;
            float wy0 = 1.0f - wy1;
            float wz0 = 1.0f - wz1;

            float v000, v001, v010, v011, v100, v101, v110, v111;

            unsigned sux = (unsigned)(ix0 - xlo);
            unsigned suy = (unsigned)(iy0 - ylo);
            unsigned suz = (unsigned)(iz0 - zlo);

            if (sux <= (unsigned)(SX - 2) &&
                suy <= (unsigned)(SY - 2) &&
                suz <= (unsigned)(SZ - 2)) {
                int sy_step = (iy1 - iy0) * SZP;   // 0 or 23
                int sx_step = (ix1 - ix0) * (SY * SZP);
                int sz_step = iz1 - iz0;           // 0 or 1
                const float* t00 = &tile[((int)sux * SY + (int)suy) * SZP + (int)suz];
                const float* t01 = t00 + sy_step;
                const float* t10 = t00 + sx_step;
                const float* t11 = t10 + sy_step;
                v000 = t00[0]; v001 = t00[sz_step];
                v010 = t01[0]; v011 = t01[sz_step];
                v100 = t10[0]; v101 = t10[sz_step];
                v110 = t11[0]; v111 = t11[sz_step];
            } else {
                // rare exact global fallback
                const float* p00 = v + ((size_t)ix0 * DY + iy0) * DZ;
                const float* p01 = v + ((size_t)ix0 * DY + iy1) * DZ;
                const float* p10 = v + ((size_t)ix1 * DY + iy0) * DZ;
                const float* p11 = v + ((size_t)ix1 * DY + iy1) * DZ;
                v000 = __ldg(p00 + iz0); v001 = __ldg(p00 + iz1);
                v010 = __ldg(p01 + iz0); v011 = __ldg(p01 + iz1);
                v100 = __ldg(p10 + iz0); v101 = __ldg(p10 + iz1);
                v110 = __ldg(p11 + iz0); v111 = __ldg(p11 + iz1);
            }

            float c00 = v000 * wz1 + v001 * wz0;
            float c01 = v010 * wz1 + v011 * wz0;
            float c10 = v100 * wz1 + v101 * wz0;
            float c11 = v110 * wz1 + v111 * wz0;

            float c0 = c00 * wy1 + c01 * wy0;
            float c1 = c10 * wy1 + c11 * wy0;

            rp[j] = c0 * wx1 + c1 * wx0;
        }

        out4[g] = res;
    }
}

extern "C" void kernel_launch(void* const* d_in, const int* in_sizes, int n_in,
                              void* d_out, int out_size)
{
    const float* vol = (const float*)d_in[0];
    const float* trf = (const float*)d_in[1];
    float* out = (float*)d_out;

    cudaFuncSetAttribute(warp_tile8_kernel,
                         cudaFuncAttributeMaxDynamicSharedMemorySize,
                         SELEMS * (int)sizeof(float));

    dim3 grid(DZ / TS, DY / TS, NB * (DX / TS));  // (10, 12, 20)
    warp_tile8_kernel<<<grid, 256, SELEMS * sizeof(float)>>>(vol, trf, out);
}

// round 9
// speedup vs baseline: 1.1661x; 1.1334x over previous
#include <cuda_runtime.h>

// SpatialTransformer: 3D trilinear warp, smem-tiled, ILP-4 (R3 base config),
// with inner-loop issue-work reduction: 32-bit additive indexing and
// __float2int_rd instead of floorf. Layout and math identical to the
// 72.1us R3 kernel (tile 22x22x24, SZP=25, 4 blocks/SM).

#define DX 160
#define DY 192
#define DZ 160
#define NB 2
#define TS 16
#define SX 22          // tile extent in x
#define SY 22          // tile extent in y
#define SZ 24          // tile extent in z (values [z0-4 .. z0+19])
#define SZP 25         // padded z row stride
#define SELEMS (SX*SY*SZP)   // 12100 floats = 48400 B

extern __shared__ float tile[];

__device__ __forceinline__ int iclamp(int v, int hi) {
    return min(max(v, 0), hi);
}

__global__ __launch_bounds__(256, 4)
void warp_tile9_kernel(const float* __restrict__ vol,
                       const float* __restrict__ trf,
                       float* __restrict__ out)
{
    const int tid = threadIdx.x;
    const int b  = blockIdx.z / (DX / TS);
    const int x0 = (blockIdx.z % (DX / TS)) * TS;
    const int y0 = blockIdx.y * TS;
    const int z0 = blockIdx.x * TS;

    const float* __restrict__ v = vol + (size_t)b * (DX * DY * DZ);
    const int xlo = x0 - 3, ylo = y0 - 3, zlo = z0 - 4;

    // ---------------- cooperative tile load ----------------
    if (zlo >= 0 && z0 + 19 <= DZ - 1) {
        // z-interior: 24 z values = 6 aligned float4 per (x,y) row
        for (int idx = tid; idx < SX * SY * 6; idx += 256) {
            int c   = idx % 6;
            int row = idx / 6;
            int py  = row % SY;
            int px  = row / SY;
            int gx  = iclamp(xlo + px, DX - 1);
            int gy  = iclamp(ylo + py, DY - 1);
            float4 val = __ldg(reinterpret_cast<const float4*>(
                                   v + ((size_t)gx * DY + gy) * DZ + zlo) + c);
            float* dst = &tile[(px * SY + py) * SZP + c * 4];
            dst[0] = val.x; dst[1] = val.y; dst[2] = val.z; dst[3] = val.w;
        }
    } else {
        // z-border: scalar clamped load
        for (int idx = tid; idx < SX * SY * SZ; idx += 256) {
            int pz = idx % SZ;
            int r  = idx / SZ;
            int py = r % SY;
            int px = r / SY;
            int gx = iclamp(xlo + px, DX - 1);
            int gy = iclamp(ylo + py, DY - 1);
            int gz = iclamp(zlo + pz, DZ - 1);
            tile[(px * SY + py) * SZP + pz] =
                __ldg(v + ((size_t)gx * DY + gy) * DZ + gz);
        }
    }
    __syncthreads();

    // ---------------- per-voxel warp, 4 z-voxels per thread ----------------
    const int zg = tid & 3;            // z quad within tile (0..3)
    const int vy = (tid >> 2) & 15;    // 0..15
    const int xs = tid >> 6;           // 0..3
    const int gy = y0 + vy;
    const int zb = z0 + zg * 4;

    // 32-bit group index; max value < 2.46M, fits easily.
    unsigned g = (unsigned)((((b * DX + x0 + xs) * DY + gy) * (DZ / 4))
                            + (z0 >> 2) + zg);
    const unsigned gstep = (unsigned)(DY * DZ);   // delta when gx += 4

    const float4* __restrict__ trf4 = reinterpret_cast<const float4*>(trf);
    float4* __restrict__ out4 = reinterpret_cast<float4*>(out);

#pragma unroll 1
    for (int it = 0; it < 4; ++it, g += gstep) {
        const int gx = x0 + it * 4 + xs;

        float4 t0 = __ldg(&trf4[g * 3u + 0u]);
        float4 t1 = __ldg(&trf4[g * 3u + 1u]);
        float4 t2 = __ldg(&trf4[g * 3u + 2u]);

        float tx[4] = {t0.x, t0.w, t1.z, t2.y};
        float ty[4] = {t0.y, t1.x, t1.w, t2.z};
        float tz[4] = {t0.z, t1.y, t2.x, t2.w};

        float4 res;
        float* rp = reinterpret_cast<float*>(&res);

#pragma unroll
        for (int j = 0; j < 4; ++j) {
            float lx = fminf(fmaxf((float)gx + tx[j],       0.0f), (float)(DX - 1));
            float ly = fminf(fmaxf((float)gy + ty[j],       0.0f), (float)(DY - 1));
            float lz = fminf(fmaxf((float)(zb + j) + tz[j], 0.0f), (float)(DZ - 1));

            int ix0 = __float2int_rd(lx);
            int iy0 = __float2int_rd(ly);
            int iz0 = __float2int_rd(lz);
            int ix1 = min(ix0 + 1, DX - 1);
            int iy1 = min(iy0 + 1, DY - 1);
            int iz1 = min(iz0 + 1, DZ - 1);

            float wx1 = (float)ix1 - lx;    // lower-corner weight (d1)
            float wy1 = (float)iy1 - ly;
            float wz1 = (float)iz1 - lz;
            float wx0 = 1.0f - wx1;
            float wy0 = 1.0f - wy1;
            float wz0 = 1.0f - wz1;

            float v000, v001, v010, v011, v100, v101, v110, v111;

            unsigned sux = (unsigned)(ix0 - xlo);
            unsigned suy = (unsigned)(iy0 - ylo);
            unsigned suz = (unsigned)(iz0 - zlo);

            if (sux <= (unsigned)(SX - 2) &&
                suy <= (unsigned)(SY - 2) &&
                suz <= (unsigned)(SZ - 2)) {
                int sy_step = (iy1 - iy0) * SZP;   // 0 or 25
                int sx_step = (ix1 - ix0) * (SY * SZP);
                int sz_step = iz1 - iz0;           // 0 or 1
                const float* t00 = &tile[(sux * SY + suy) * SZP + suz];
                const float* t01 = t00 + sy_step;
                const float* t10 = t00 + sx_step;
                const float* t11 = t10 + sy_step;
                v000 = t00[0]; v001 = t00[sz_step];
                v010 = t01[0]; v011 = t01[sz_step];
                v100 = t10[0]; v101 = t10[sz_step];
                v110 = t11[0]; v111 = t11[sz_step];
            } else {
                // rare exact global fallback
                const float* p00 = v + ((size_t)ix0 * DY + iy0) * DZ;
                const float* p01 = v + ((size_t)ix0 * DY + iy1) * DZ;
                const float* p10 = v + ((size_t)ix1 * DY + iy0) * DZ;
                const float* p11 = v + ((size_t)ix1 * DY + iy1) * DZ;
                v000 = __ldg(p00 + iz0); v001 = __ldg(p00 + iz1);
                v010 = __ldg(p01 + iz0); v011 = __ldg(p01 + iz1);
                v100 = __ldg(p10 + iz0); v101 = __ldg(p10 + iz1);
                v110 = __ldg(p11 + iz0); v111 = __ldg(p11 + iz1);
            }

            float c00 = v000 * wz1 + v001 * wz0;
            float c01 = v010 * wz1 + v011 * wz0;
            float c10 = v100 * wz1 + v101 * wz0;
            float c11 = v110 * wz1 + v111 * wz0;

            float c0 = c00 * wy1 + c01 * wy0;
            float c1 = c10 * wy1 + c11 * wy0;

            rp[j] = c0 * wx1 + c1 * wx0;
        }

        out4[g] = res;
    }
}

extern "C" void kernel_launch(void* const* d_in, const int* in_sizes, int n_in,
                              void* d_out, int out_size)
{
    const float* vol = (const float*)d_in[0];
    const float* trf = (const float*)d_in[1];
    float* out = (float*)d_out;

    cudaFuncSetAttribute(warp_tile9_kernel,
                         cudaFuncAttributeMaxDynamicSharedMemorySize,
                         SELEMS * (int)sizeof(float));

    dim3 grid(DZ / TS, DY / TS, NB * (DX / TS));  // (10, 12, 20)
    warp_tile9_kernel<<<grid, 256, SELEMS * sizeof(float)>>>(vol, trf, out);
}